// round 1
// baseline (speedup 1.0000x reference)
#include <cuda_runtime.h>
#include <math.h>

#define Bsz 8192
#define Dd  1024
#define Rr  64
#define TB  16
#define NT  512

// ---- Yoshida 4th-order coefficients (double-precision, then rounded once to f32,
//      matching JAX's python-double scalar folding before the f32 broadcast) ----
constexpr double kCbrt2 = 1.2599210498948731647672106072782;
constexpr double kW1 = 1.0 / (2.0 - kCbrt2);
constexpr double kW0 = -kCbrt2 * kW1;
constexpr double kDT = 0.01;   // DT * DT_SCALE

#define C1DT ((float)((kW1 * 0.5) * kDT))
#define C2DT ((float)(((kW0 + kW1) * 0.5) * kDT))
#define C3DT C2DT
#define C4DT C1DT
#define D1DT ((float)(kW1 * kDT))
#define D2DT ((float)(kW0 * kDT))
#define D3DT D1DT

#define PLASTICITY   0.1f
#define SING_THRESH  10.0f
#define SING_STRENGTH 20.0f

__global__ void __launch_bounds__(NT, 1)
yoshida_kernel(const float* __restrict__ x_in,
               const float* __restrict__ v_in,
               const float* __restrict__ force,
               const float* __restrict__ U,     // [D, R]
               const float* __restrict__ Wm,    // [R, D]
               const float* __restrict__ Vw,    // [D, R]
               const int*   __restrict__ steps_p,
               float* __restrict__ out)         // [x(B*D) ; v(B*D)]
{
    extern __shared__ float smem[];
    float* xs     = smem;                 // TB*Dd
    float* vs     = smem + TB * Dd;       // TB*Dd
    float* qs     = vs   + TB * Dd;       // Rr*TB  (layout qs[r*TB + row])
    float* sing_s = qs   + Rr * TB;       // TB

    const int tid  = threadIdx.x;
    const int row0 = blockIdx.x * TB;

    float4* sx4 = (float4*)xs;
    float4* sv4 = (float4*)vs;

    // ---- load state tile into SMEM ----
    {
        const float4* gx = (const float4*)(x_in + (size_t)row0 * Dd);
        const float4* gv = (const float4*)(v_in + (size_t)row0 * Dd);
        #pragma unroll
        for (int i = tid; i < TB * Dd / 4; i += NT) {
            sx4[i] = gx[i];
            sv4[i] = gv[i];
        }
    }

    const int nsteps = *steps_p;

    for (int s = 0; s < nsteps; ++s) {
        #pragma unroll
        for (int sub = 0; sub < 3; ++sub) {
            const float cdt = (sub == 0) ? C1DT : (sub == 1) ? C2DT : C3DT;
            const float ddt = (sub == 0) ? D1DT : (sub == 1) ? D2DT : D3DT;

            // ---- drift: x += cdt * v ----
            __syncthreads();
            #pragma unroll
            for (int i = tid; i < TB * Dd / 4; i += NT) {
                float4 xv = sx4[i];
                const float4 vv = sv4[i];
                xv.x += cdt * vv.x; xv.y += cdt * vv.y;
                xv.z += cdt * vv.z; xv.w += cdt * vv.w;
                sx4[i] = xv;
            }
            __syncthreads();

            // ---- kick phase 1: xn2 per row -> sing_s (one warp per row) ----
            {
                const int row  = tid >> 5;
                const int lane = tid & 31;
                const float4* xr = (const float4*)(xs + row * Dd);
                float acc = 0.0f;
                #pragma unroll
                for (int i = 0; i < 8; ++i) {
                    const float4 xv = xr[lane + i * 32];
                    acc += xv.x * xv.x + xv.y * xv.y + xv.z * xv.z + xv.w * xv.w;
                }
                #pragma unroll
                for (int o = 16; o; o >>= 1)
                    acc += __shfl_xor_sync(0xffffffffu, acc, o);
                if (lane == 0)
                    sing_s[row] = 1.0f + SING_STRENGTH * expf(-acc * (1.0f / SING_THRESH));
            }

            // ---- kick phase 2: P = v.U, M = x.Vw ; q = P^2 * (1 + 0.1*tanh(M)) ----
            {
                const int r = tid & 63;
                const int g = tid >> 6;          // 0..7 -> rows {g, g+8}
                const float* __restrict__ v0 = vs + (g    ) * Dd;
                const float* __restrict__ v1 = vs + (g + 8) * Dd;
                const float* __restrict__ x0 = xs + (g    ) * Dd;
                const float* __restrict__ x1 = xs + (g + 8) * Dd;

                float p0 = 0.f, p1 = 0.f, m0 = 0.f, m1 = 0.f;
                #pragma unroll 2
                for (int d = 0; d < Dd; d += 4) {
                    const float* up = U  + (size_t)d * Rr + r;
                    const float* wp = Vw + (size_t)d * Rr + r;
                    const float u0 = up[0], u1 = up[Rr], u2 = up[2 * Rr], u3 = up[3 * Rr];
                    const float w0 = wp[0], w1 = wp[Rr], w2 = wp[2 * Rr], w3 = wp[3 * Rr];
                    float4 t;
                    t = *(const float4*)(v0 + d);
                    p0 += t.x * u0 + t.y * u1 + t.z * u2 + t.w * u3;
                    t = *(const float4*)(v1 + d);
                    p1 += t.x * u0 + t.y * u1 + t.z * u2 + t.w * u3;
                    t = *(const float4*)(x0 + d);
                    m0 += t.x * w0 + t.y * w1 + t.z * w2 + t.w * w3;
                    t = *(const float4*)(x1 + d);
                    m1 += t.x * w0 + t.y * w1 + t.z * w2 + t.w * w3;
                }
                qs[r * TB + g    ] = p0 * p0 * (1.0f + PLASTICITY * tanhf(m0));
                qs[r * TB + g + 8] = p1 * p1 * (1.0f + PLASTICITY * tanhf(m1));
            }
            __syncthreads();

            // ---- kick phase 3: gamma = q.W ; v += ddt * (force - gamma*sing) ----
            {
                const int kk = (tid & 127) * 4;       // 128 k-threads * 4 k = 512 k / pass
                const int g4 = (tid >> 7) * 4;        // rows g4..g4+3
                #pragma unroll
                for (int pass = 0; pass < 2; ++pass) {
                    const int k0 = pass * 512 + kk;
                    float4 a0 = {0,0,0,0}, a1 = {0,0,0,0}, a2 = {0,0,0,0}, a3 = {0,0,0,0};
                    #pragma unroll 8
                    for (int r = 0; r < Rr; ++r) {
                        const float4 w = *(const float4*)(Wm + (size_t)r * Dd + k0);
                        const float4 q = *(const float4*)(qs + r * TB + g4);
                        a0.x += q.x * w.x; a0.y += q.x * w.y; a0.z += q.x * w.z; a0.w += q.x * w.w;
                        a1.x += q.y * w.x; a1.y += q.y * w.y; a1.z += q.y * w.z; a1.w += q.y * w.w;
                        a2.x += q.z * w.x; a2.y += q.z * w.y; a2.z += q.z * w.z; a2.w += q.z * w.w;
                        a3.x += q.w * w.x; a3.y += q.w * w.y; a3.z += q.w * w.z; a3.w += q.w * w.w;
                    }
                    #pragma unroll
                    for (int j = 0; j < 4; ++j) {
                        const int row = g4 + j;
                        const float sg = sing_s[row];
                        const float4 a = (j == 0) ? a0 : (j == 1) ? a1 : (j == 2) ? a2 : a3;
                        const float4 f = *(const float4*)(force + (size_t)(row0 + row) * Dd + k0);
                        float4* vp = (float4*)(vs + row * Dd + k0);
                        float4 vv = *vp;
                        vv.x += ddt * (f.x - a.x * sg);
                        vv.y += ddt * (f.y - a.y * sg);
                        vv.z += ddt * (f.z - a.z * sg);
                        vv.w += ddt * (f.w - a.w * sg);
                        *vp = vv;
                    }
                }
            }
        }

        // ---- final drift of the step: x += C4*dt * v ----
        __syncthreads();
        #pragma unroll
        for (int i = tid; i < TB * Dd / 4; i += NT) {
            float4 xv = sx4[i];
            const float4 vv = sv4[i];
            xv.x += C4DT * vv.x; xv.y += C4DT * vv.y;
            xv.z += C4DT * vv.z; xv.w += C4DT * vv.w;
            sx4[i] = xv;
        }
    }

    // ---- store: out = [x ; v] ----
    __syncthreads();
    {
        float4* ox = (float4*)(out + (size_t)row0 * Dd);
        float4* ov = (float4*)(out + (size_t)Bsz * Dd + (size_t)row0 * Dd);
        #pragma unroll
        for (int i = tid; i < TB * Dd / 4; i += NT) {
            ox[i] = sx4[i];
            ov[i] = sv4[i];
        }
    }
}

extern "C" void kernel_launch(void* const* d_in, const int* in_sizes, int n_in,
                              void* d_out, int out_size) {
    const float* x     = (const float*)d_in[0];
    const float* v     = (const float*)d_in[1];
    const float* force = (const float*)d_in[2];
    const float* U     = (const float*)d_in[3];
    const float* W     = (const float*)d_in[4];
    const float* Vw    = (const float*)d_in[5];
    const int*   steps = (const int*)d_in[6];

    const size_t smem = (size_t)(2 * TB * Dd + Rr * TB + TB) * sizeof(float);
    cudaFuncSetAttribute(yoshida_kernel,
                         cudaFuncAttributeMaxDynamicSharedMemorySize, (int)smem);
    yoshida_kernel<<<Bsz / TB, NT, smem>>>(x, v, force, U, W, Vw, steps, (float*)d_out);
}